// round 5
// baseline (speedup 1.0000x reference)
#include <cuda_runtime.h>

#define NVERT 8192
#define GRES 64
#define NVOX (GRES*GRES*GRES)   // 262144
#define NMAX 1048576
#define SCANB 512               // 512 blocks x 512 threads covers NVOX

// ---------------- scratch (device globals; no allocation) ----------------
__device__ unsigned int g_mm[6];        // sortable-uint min(x,y,z), max(x,y,z)
__device__ int g_hist[NVOX];
__device__ int g_off[NVOX + 1];
__device__ int g_cur[NVOX];
__device__ int g_bsum[SCANB];
__device__ int g_bbase[SCANB];
__device__ int g_vid[NMAX];
__device__ int g_perm[NMAX];
__device__ float4 g_vert[NVERT];        // {x, y, z, |v|^2}

// monotone float<->uint mapping (min/max via integer atomics)
__device__ __forceinline__ unsigned f2o(float f) {
    unsigned b = __float_as_uint(f);
    return (b & 0x80000000u) ? ~b : (b | 0x80000000u);
}
__device__ __forceinline__ float o2f(unsigned o) {
    unsigned b = (o & 0x80000000u) ? (o & 0x7FFFFFFFu) : ~o;
    return __uint_as_float(b);
}

// ---------------- 1. init scratch ----------------
__global__ void k_init() {
    int i = blockIdx.x * blockDim.x + threadIdx.x;
    int stride = gridDim.x * blockDim.x;
    for (int j = i; j < NVOX; j += stride) g_hist[j] = 0;
    if (i < 3) g_mm[i] = 0xFFFFFFFFu;
    else if (i < 6) g_mm[i] = 0u;
}

// ---------------- 2. global min/max per coordinate ----------------
__global__ void k_minmax(const float* __restrict__ xyz, int n) {
    float mnx = 3.402823466e38f, mny = mnx, mnz = mnx;
    float mxx = -3.402823466e38f, mxy = mxx, mxz = mxx;
    for (int i = blockIdx.x * blockDim.x + threadIdx.x; i < n;
         i += gridDim.x * blockDim.x) {
        float x = xyz[3 * i], y = xyz[3 * i + 1], z = xyz[3 * i + 2];
        mnx = fminf(mnx, x); mny = fminf(mny, y); mnz = fminf(mnz, z);
        mxx = fmaxf(mxx, x); mxy = fmaxf(mxy, y); mxz = fmaxf(mxz, z);
    }
    for (int o = 16; o; o >>= 1) {
        mnx = fminf(mnx, __shfl_xor_sync(0xFFFFFFFFu, mnx, o));
        mny = fminf(mny, __shfl_xor_sync(0xFFFFFFFFu, mny, o));
        mnz = fminf(mnz, __shfl_xor_sync(0xFFFFFFFFu, mnz, o));
        mxx = fmaxf(mxx, __shfl_xor_sync(0xFFFFFFFFu, mxx, o));
        mxy = fmaxf(mxy, __shfl_xor_sync(0xFFFFFFFFu, mxy, o));
        mxz = fmaxf(mxz, __shfl_xor_sync(0xFFFFFFFFu, mxz, o));
    }
    if ((threadIdx.x & 31) == 0) {
        atomicMin(&g_mm[0], f2o(mnx));
        atomicMin(&g_mm[1], f2o(mny));
        atomicMin(&g_mm[2], f2o(mnz));
        atomicMax(&g_mm[3], f2o(mxx));
        atomicMax(&g_mm[4], f2o(mxy));
        atomicMax(&g_mm[5], f2o(mxz));
    }
}

// ---------------- 3. voxel id + histogram (reciprocal-hoisted division) ----
// LLVM/XLA:CPU hoists the loop-invariant divisor: u = (x-mn) * RN(1/d),
// two roundings. This is the only remaining IEEE-plausible divergence after
// eliminating sel (3 variants) and ordering (provably stable-exact).
__global__ void k_vidhist(const float* __restrict__ xyz, int n) {
    float mnx = o2f(g_mm[0]), mny = o2f(g_mm[1]), mnz = o2f(g_mm[2]);
    float exx = __fsub_rn(o2f(g_mm[3]), mnx);
    float exy = __fsub_rn(o2f(g_mm[4]), mny);
    float exz = __fsub_rn(o2f(g_mm[5]), mnz);
    float dx = exx > 0.f ? exx : 1.f;
    float dy = exy > 0.f ? exy : 1.f;
    float dz = exz > 0.f ? exz : 1.f;
    float rx = __fdiv_rn(1.0f, dx);   // hoisted exact reciprocal
    float ry = __fdiv_rn(1.0f, dy);
    float rz = __fdiv_rn(1.0f, dz);
    const float HI = (float)(1.0 - 1e-6);
    for (int i = blockIdx.x * blockDim.x + threadIdx.x; i < n;
         i += gridDim.x * blockDim.x) {
        float ux = __fmul_rn(__fsub_rn(xyz[3 * i],     mnx), rx);
        float uy = __fmul_rn(__fsub_rn(xyz[3 * i + 1], mny), ry);
        float uz = __fmul_rn(__fsub_rn(xyz[3 * i + 2], mnz), rz);
        ux = fminf(fmaxf(ux, 0.f), HI);
        uy = fminf(fmaxf(uy, 0.f), HI);
        uz = fminf(fmaxf(uz, 0.f), HI);
        int vx = (int)floorf(__fmul_rn(ux, (float)GRES));
        int vy = (int)floorf(__fmul_rn(uy, (float)GRES));
        int vz = (int)floorf(__fmul_rn(uz, (float)GRES));
        int vid = (vx * GRES + vy) * GRES + vz;
        g_vid[i] = vid;
        atomicAdd(&g_hist[vid], 1);
    }
}

// ---------------- 4. exclusive scan of histogram (3 kernels) ----------------
__global__ void k_scan_a() {
    __shared__ int sh[512];
    int i = blockIdx.x * 512 + threadIdx.x;
    sh[threadIdx.x] = g_hist[i];
    __syncthreads();
    for (int off = 256; off; off >>= 1) {
        if (threadIdx.x < off) sh[threadIdx.x] += sh[threadIdx.x + off];
        __syncthreads();
    }
    if (threadIdx.x == 0) g_bsum[blockIdx.x] = sh[0];
}
__global__ void k_scan_b(int n) {
    __shared__ int sh[512];
    int v = g_bsum[threadIdx.x];
    sh[threadIdx.x] = v;
    __syncthreads();
    for (int off = 1; off < 512; off <<= 1) {
        int t = (threadIdx.x >= off) ? sh[threadIdx.x - off] : 0;
        __syncthreads();
        sh[threadIdx.x] += t;
        __syncthreads();
    }
    g_bbase[threadIdx.x] = sh[threadIdx.x] - v;
    if (threadIdx.x == 0) g_off[NVOX] = n;
}
__global__ void k_scan_c() {
    __shared__ int sh[512];
    int i = blockIdx.x * 512 + threadIdx.x;
    int v = g_hist[i];
    sh[threadIdx.x] = v;
    __syncthreads();
    for (int off = 1; off < 512; off <<= 1) {
        int t = (threadIdx.x >= off) ? sh[threadIdx.x - off] : 0;
        __syncthreads();
        sh[threadIdx.x] += t;
        __syncthreads();
    }
    int excl = sh[threadIdx.x] - v + g_bbase[blockIdx.x];
    g_off[i] = excl;
    g_cur[i] = excl;
}

// ---------------- 5. counting-sort scatter (unstable within bucket) --------
__global__ void k_scatter(int n) {
    for (int i = blockIdx.x * blockDim.x + threadIdx.x; i < n;
         i += gridDim.x * blockDim.x) {
        int v = g_vid[i];
        int pos = atomicAdd(&g_cur[v], 1);
        g_perm[pos] = i;
    }
}

// ---------------- 6. stable selection of 8192 vertices --------------------
// sel per f32 jnp.linspace: delta = RN((n-1)/8191); s = floor(RN(q*delta)).
// (Empirically the best of three formulations tested — r1.)
__global__ void k_select(const float* __restrict__ xyz,
                         float* __restrict__ out, int n) {
    __shared__ int sb[4096];
    __shared__ int info[3];
    int q = blockIdx.x;
    if (threadIdx.x == 0) {
        float delta = __fdiv_rn((float)(n - 1), (float)(NVERT - 1));
        float fv = __fmul_rn((float)q, delta);
        int s = (int)floorf(fv);
        int lo = 0, hi = NVOX;
        while (hi - lo > 1) {
            int mid = (lo + hi) >> 1;
            if (g_off[mid] <= s) lo = mid; else hi = mid;
        }
        info[0] = g_off[lo];
        info[1] = g_off[lo + 1] - g_off[lo];
        info[2] = s - g_off[lo];
    }
    __syncthreads();
    int base = info[0], m = info[1], r = info[2];

    if (m <= 4096) {
        for (int j = threadIdx.x; j < m; j += blockDim.x) sb[j] = g_perm[base + j];
        __syncthreads();
        for (int j = threadIdx.x; j < m; j += blockDim.x) {
            int x = sb[j], c = 0;
            for (int t = 0; t < m; t++) c += (sb[t] < x);
            if (c == r) {
                float vx = xyz[3 * x], vy = xyz[3 * x + 1], vz = xyz[3 * x + 2];
                out[3 * q] = vx; out[3 * q + 1] = vy; out[3 * q + 2] = vz;
                float vn = __fadd_rn(__fadd_rn(__fmul_rn(vx, vx), __fmul_rn(vy, vy)),
                                     __fmul_rn(vz, vz));
                g_vert[q] = make_float4(vx, vy, vz, vn);
            }
        }
    } else {
        for (int j = threadIdx.x; j < m; j += blockDim.x) {
            int x = g_perm[base + j], c = 0;
            for (int t = 0; t < m; t++) c += (g_perm[base + t] < x);
            if (c == r) {
                float vx = xyz[3 * x], vy = xyz[3 * x + 1], vz = xyz[3 * x + 2];
                out[3 * q] = vx; out[3 * q + 1] = vy; out[3 * q + 2] = vz;
                float vn = __fadd_rn(__fadd_rn(__fmul_rn(vx, vx), __fmul_rn(vy, vy)),
                                     __fmul_rn(vz, vz));
                g_vert[q] = make_float4(vx, vy, vz, vn);
            }
        }
    }
}

// ---------------- 7. brute-force 1-NN (dominant kernel) --------------------
// dot = fma(z,Z, fma(y,Y, RN(x*X))); d = RN(vn - RN(2*dot)); first-wins argmin.
__global__ void __launch_bounds__(256, 1)
k_knn(const float* __restrict__ xyz, float* __restrict__ out, int n) {
    extern __shared__ float4 sv[];
    for (int j = threadIdx.x; j < NVERT; j += blockDim.x) sv[j] = g_vert[j];
    __syncthreads();

    int chunk = (n + gridDim.x - 1) / gridDim.x;
    int start = blockIdx.x * chunk;
    int end = min(start + chunk, n);
    float* pout = out + 3 * NVERT;

    for (int p0 = start + (int)threadIdx.x; p0 < end; p0 += 4 * 256) {
        int pA = p0;
        int pB = min(p0 + 256, end - 1);
        int pC = min(p0 + 512, end - 1);
        int pD = min(p0 + 768, end - 1);
        float ax = xyz[3 * pA], ay = xyz[3 * pA + 1], az = xyz[3 * pA + 2];
        float bx = xyz[3 * pB], by = xyz[3 * pB + 1], bz = xyz[3 * pB + 2];
        float cx = xyz[3 * pC], cy = xyz[3 * pC + 1], cz = xyz[3 * pC + 2];
        float dx = xyz[3 * pD], dy = xyz[3 * pD + 1], dz = xyz[3 * pD + 2];

        float bA = 3.402823466e38f, bB = bA, bC = bA, bD = bA;
        int jA = 0, jB = 0, jC = 0, jD = 0;

#pragma unroll 4
        for (int v = 0; v < NVERT; v++) {
            float4 V = sv[v];
            float tA = fmaf(az, V.z, fmaf(ay, V.y, __fmul_rn(ax, V.x)));
            float tB = fmaf(bz, V.z, fmaf(by, V.y, __fmul_rn(bx, V.x)));
            float tC = fmaf(cz, V.z, fmaf(cy, V.y, __fmul_rn(cx, V.x)));
            float tD = fmaf(dz, V.z, fmaf(dy, V.y, __fmul_rn(dx, V.x)));
            float dA = __fsub_rn(V.w, __fmul_rn(2.0f, tA));
            float dB = __fsub_rn(V.w, __fmul_rn(2.0f, tB));
            float dC = __fsub_rn(V.w, __fmul_rn(2.0f, tC));
            float dD = __fsub_rn(V.w, __fmul_rn(2.0f, tD));
            jA = (dA < bA) ? v : jA;  bA = fminf(dA, bA);
            jB = (dB < bB) ? v : jB;  bB = fminf(dB, bB);
            jC = (dC < bC) ? v : jC;  bC = fminf(dC, bC);
            jD = (dD < bD) ? v : jD;  bD = fminf(dD, bD);
        }

        pout[pA] = (float)jA;
        if (p0 + 256 < end) pout[pB] = (float)jB;
        if (p0 + 512 < end) pout[pC] = (float)jC;
        if (p0 + 768 < end) pout[pD] = (float)jD;
    }
}

// ---------------- launch ----------------
extern "C" void kernel_launch(void* const* d_in, const int* in_sizes, int n_in,
                              void* d_out, int out_size) {
    const float* xyz = (const float*)d_in[0];
    int n = in_sizes[0] / 3;
    float* out = (float*)d_out;

    k_init<<<256, 256>>>();
    k_minmax<<<148, 256>>>(xyz, n);
    k_vidhist<<<1024, 256>>>(xyz, n);
    k_scan_a<<<SCANB, 512>>>();
    k_scan_b<<<1, 512>>>(n);
    k_scan_c<<<SCANB, 512>>>();
    k_scatter<<<1024, 256>>>(n);
    k_select<<<NVERT, 128>>>(xyz, out, n);

    cudaFuncSetAttribute(k_knn, cudaFuncAttributeMaxDynamicSharedMemorySize,
                         NVERT * (int)sizeof(float4));
    k_knn<<<148, 256, NVERT * sizeof(float4)>>>(xyz, out, n);
}

// round 6
// speedup vs baseline: 4.7311x; 4.7311x over previous
#include <cuda_runtime.h>

#define NVERT 8192
#define GRES 64
#define NVOX (GRES*GRES*GRES)   // 262144
#define NMAX 1048576
#define SCANB 512               // 512 blocks x 512 threads covers NVOX

// ---------------- scratch (device globals; no allocation) ----------------
__device__ unsigned int g_mm[6];        // sortable-uint min(x,y,z), max(x,y,z)
__device__ int g_hist[NVOX];
__device__ int g_off[NVOX + 1];
__device__ int g_cur[NVOX];
__device__ int g_bsum[SCANB];
__device__ int g_bbase[SCANB];
__device__ int g_vid[NMAX];
__device__ int g_perm[NMAX];
__device__ float4 g_vert[NVERT];        // raw {x, y, z, |v|^2}
// vertex grid for pruned knn
__device__ int v_hist[NVOX];
__device__ int v_off[NVOX + 1];
__device__ int v_cur[NVOX];
__device__ int v_cell[NVERT];
__device__ float4 g_vs[NVERT];          // sorted, prescaled {2x,2y,2z,|v|^2}
__device__ unsigned short g_vsidx[NVERT];

// monotone float<->uint mapping (min/max via integer atomics)
__device__ __forceinline__ unsigned f2o(float f) {
    unsigned b = __float_as_uint(f);
    return (b & 0x80000000u) ? ~b : (b | 0x80000000u);
}
__device__ __forceinline__ float o2f(unsigned o) {
    unsigned b = (o & 0x80000000u) ? (o & 0x7FFFFFFFu) : ~o;
    return __uint_as_float(b);
}

// shared helper: per-axis extent guards (must match k_vidhist exactly)
__device__ __forceinline__ void grid_params(float& mnx, float& mny, float& mnz,
                                            float& dx, float& dy, float& dz) {
    mnx = o2f(g_mm[0]); mny = o2f(g_mm[1]); mnz = o2f(g_mm[2]);
    float exx = __fsub_rn(o2f(g_mm[3]), mnx);
    float exy = __fsub_rn(o2f(g_mm[4]), mny);
    float exz = __fsub_rn(o2f(g_mm[5]), mnz);
    dx = exx > 0.f ? exx : 1.f;
    dy = exy > 0.f ? exy : 1.f;
    dz = exz > 0.f ? exz : 1.f;
}

// ---------------- 1. init scratch ----------------
__global__ void k_init() {
    int i = blockIdx.x * blockDim.x + threadIdx.x;
    int stride = gridDim.x * blockDim.x;
    for (int j = i; j < NVOX; j += stride) { g_hist[j] = 0; v_hist[j] = 0; }
    if (i < 3) g_mm[i] = 0xFFFFFFFFu;
    else if (i < 6) g_mm[i] = 0u;
}

// ---------------- 2. global min/max per coordinate ----------------
__global__ void k_minmax(const float* __restrict__ xyz, int n) {
    float mnx = 3.402823466e38f, mny = mnx, mnz = mnx;
    float mxx = -3.402823466e38f, mxy = mxx, mxz = mxx;
    for (int i = blockIdx.x * blockDim.x + threadIdx.x; i < n;
         i += gridDim.x * blockDim.x) {
        float x = xyz[3 * i], y = xyz[3 * i + 1], z = xyz[3 * i + 2];
        mnx = fminf(mnx, x); mny = fminf(mny, y); mnz = fminf(mnz, z);
        mxx = fmaxf(mxx, x); mxy = fmaxf(mxy, y); mxz = fmaxf(mxz, z);
    }
    for (int o = 16; o; o >>= 1) {
        mnx = fminf(mnx, __shfl_xor_sync(0xFFFFFFFFu, mnx, o));
        mny = fminf(mny, __shfl_xor_sync(0xFFFFFFFFu, mny, o));
        mnz = fminf(mnz, __shfl_xor_sync(0xFFFFFFFFu, mnz, o));
        mxx = fmaxf(mxx, __shfl_xor_sync(0xFFFFFFFFu, mxx, o));
        mxy = fmaxf(mxy, __shfl_xor_sync(0xFFFFFFFFu, mxy, o));
        mxz = fmaxf(mxz, __shfl_xor_sync(0xFFFFFFFFu, mxz, o));
    }
    if ((threadIdx.x & 31) == 0) {
        atomicMin(&g_mm[0], f2o(mnx));
        atomicMin(&g_mm[1], f2o(mny));
        atomicMin(&g_mm[2], f2o(mnz));
        atomicMax(&g_mm[3], f2o(mxx));
        atomicMax(&g_mm[4], f2o(mxy));
        atomicMax(&g_mm[5], f2o(mxz));
    }
}

// ---------------- 3. voxel id + histogram (reciprocal-hoisted division) ----
__global__ void k_vidhist(const float* __restrict__ xyz, int n) {
    float mnx, mny, mnz, dx, dy, dz;
    grid_params(mnx, mny, mnz, dx, dy, dz);
    float rx = __fdiv_rn(1.0f, dx);
    float ry = __fdiv_rn(1.0f, dy);
    float rz = __fdiv_rn(1.0f, dz);
    const float HI = (float)(1.0 - 1e-6);
    for (int i = blockIdx.x * blockDim.x + threadIdx.x; i < n;
         i += gridDim.x * blockDim.x) {
        float ux = __fmul_rn(__fsub_rn(xyz[3 * i],     mnx), rx);
        float uy = __fmul_rn(__fsub_rn(xyz[3 * i + 1], mny), ry);
        float uz = __fmul_rn(__fsub_rn(xyz[3 * i + 2], mnz), rz);
        ux = fminf(fmaxf(ux, 0.f), HI);
        uy = fminf(fmaxf(uy, 0.f), HI);
        uz = fminf(fmaxf(uz, 0.f), HI);
        int vx = (int)floorf(__fmul_rn(ux, (float)GRES));
        int vy = (int)floorf(__fmul_rn(uy, (float)GRES));
        int vz = (int)floorf(__fmul_rn(uz, (float)GRES));
        int vid = (vx * GRES + vy) * GRES + vz;
        g_vid[i] = vid;
        atomicAdd(&g_hist[vid], 1);
    }
}

// ---------------- 4. generic exclusive scan over NVOX (3 kernels) ----------
__global__ void k_scan_a(const int* __restrict__ hist) {
    __shared__ int sh[512];
    int i = blockIdx.x * 512 + threadIdx.x;
    sh[threadIdx.x] = hist[i];
    __syncthreads();
    for (int off = 256; off; off >>= 1) {
        if (threadIdx.x < off) sh[threadIdx.x] += sh[threadIdx.x + off];
        __syncthreads();
    }
    if (threadIdx.x == 0) g_bsum[blockIdx.x] = sh[0];
}
__global__ void k_scan_b(int* __restrict__ off, int total) {
    __shared__ int sh[512];
    int v = g_bsum[threadIdx.x];
    sh[threadIdx.x] = v;
    __syncthreads();
    for (int o = 1; o < 512; o <<= 1) {
        int t = (threadIdx.x >= o) ? sh[threadIdx.x - o] : 0;
        __syncthreads();
        sh[threadIdx.x] += t;
        __syncthreads();
    }
    g_bbase[threadIdx.x] = sh[threadIdx.x] - v;
    if (threadIdx.x == 0) off[NVOX] = total;
}
__global__ void k_scan_c(const int* __restrict__ hist, int* __restrict__ off,
                         int* __restrict__ cur) {
    __shared__ int sh[512];
    int i = blockIdx.x * 512 + threadIdx.x;
    int v = hist[i];
    sh[threadIdx.x] = v;
    __syncthreads();
    for (int o = 1; o < 512; o <<= 1) {
        int t = (threadIdx.x >= o) ? sh[threadIdx.x - o] : 0;
        __syncthreads();
        sh[threadIdx.x] += t;
        __syncthreads();
    }
    int excl = sh[threadIdx.x] - v + g_bbase[blockIdx.x];
    off[i] = excl;
    cur[i] = excl;
}

// ---------------- 5. counting-sort scatter (points) ------------------------
__global__ void k_scatter(int n) {
    for (int i = blockIdx.x * blockDim.x + threadIdx.x; i < n;
         i += gridDim.x * blockDim.x) {
        int v = g_vid[i];
        int pos = atomicAdd(&g_cur[v], 1);
        g_perm[pos] = i;
    }
}

// ---------------- 6. stable selection of 8192 vertices ---------------------
// sel per f32 jnp.linspace: delta = RN((n-1)/8191); s = floor(RN(q*delta)).
__global__ void k_select(const float* __restrict__ xyz,
                         float* __restrict__ out, int n) {
    __shared__ int sb[4096];
    __shared__ int info[3];
    int q = blockIdx.x;
    if (threadIdx.x == 0) {
        float delta = __fdiv_rn((float)(n - 1), (float)(NVERT - 1));
        float fv = __fmul_rn((float)q, delta);
        int s = (int)floorf(fv);
        int lo = 0, hi = NVOX;
        while (hi - lo > 1) {
            int mid = (lo + hi) >> 1;
            if (g_off[mid] <= s) lo = mid; else hi = mid;
        }
        info[0] = g_off[lo];
        info[1] = g_off[lo + 1] - g_off[lo];
        info[2] = s - g_off[lo];
    }
    __syncthreads();
    int base = info[0], m = info[1], r = info[2];

    if (m <= 4096) {
        for (int j = threadIdx.x; j < m; j += blockDim.x) sb[j] = g_perm[base + j];
        __syncthreads();
        for (int j = threadIdx.x; j < m; j += blockDim.x) {
            int x = sb[j], c = 0;
            for (int t = 0; t < m; t++) c += (sb[t] < x);
            if (c == r) {
                float vx = xyz[3 * x], vy = xyz[3 * x + 1], vz = xyz[3 * x + 2];
                out[3 * q] = vx; out[3 * q + 1] = vy; out[3 * q + 2] = vz;
                float vn = __fadd_rn(__fadd_rn(__fmul_rn(vx, vx), __fmul_rn(vy, vy)),
                                     __fmul_rn(vz, vz));
                g_vert[q] = make_float4(vx, vy, vz, vn);
            }
        }
    } else {
        for (int j = threadIdx.x; j < m; j += blockDim.x) {
            int x = g_perm[base + j], c = 0;
            for (int t = 0; t < m; t++) c += (g_perm[base + t] < x);
            if (c == r) {
                float vx = xyz[3 * x], vy = xyz[3 * x + 1], vz = xyz[3 * x + 2];
                out[3 * q] = vx; out[3 * q + 1] = vy; out[3 * q + 2] = vz;
                float vn = __fadd_rn(__fadd_rn(__fmul_rn(vx, vx), __fmul_rn(vy, vy)),
                                     __fmul_rn(vz, vz));
                g_vert[q] = make_float4(vx, vy, vz, vn);
            }
        }
    }
}

// ---------------- 6b. bin vertices into the 64^3 grid ----------------------
__global__ void k_vbin() {
    int q = blockIdx.x * blockDim.x + threadIdx.x;
    if (q >= NVERT) return;
    float mnx, mny, mnz, dx, dy, dz;
    grid_params(mnx, mny, mnz, dx, dy, dz);
    float ivx = __fdiv_rn((float)GRES, dx);
    float ivy = __fdiv_rn((float)GRES, dy);
    float ivz = __fdiv_rn((float)GRES, dz);
    float4 v = g_vert[q];
    int cx = min(max((int)floorf((v.x - mnx) * ivx), 0), GRES - 1);
    int cy = min(max((int)floorf((v.y - mny) * ivy), 0), GRES - 1);
    int cz = min(max((int)floorf((v.z - mnz) * ivz), 0), GRES - 1);
    int c = (cx * GRES + cy) * GRES + cz;
    v_cell[q] = c;
    atomicAdd(&v_hist[c], 1);
}

// ---------------- 6c. scatter vertices (prescaled by 2) --------------------
__global__ void k_vscatter() {
    int q = blockIdx.x * blockDim.x + threadIdx.x;
    if (q >= NVERT) return;
    int c = v_cell[q];
    int pos = atomicAdd(&v_cur[c], 1);
    float4 v = g_vert[q];
    g_vs[pos] = make_float4(2.0f * v.x, 2.0f * v.y, 2.0f * v.z, v.w);
    g_vsidx[pos] = (unsigned short)q;
}

// ---------------- 7. grid-pruned 1-NN (bit-exact argmin) -------------------
// Phase A: upper bound from 3^3 (expanding if empty). Phase B: exact rescan
// of all cells intersecting sphere(p, sqrt(bestD+1e-3)+1e-3); evaluate the
// reference float formula d = RN(vn - t2), t2 = fma(pz,2Vz,fma(py,2Vy,
// RN(px*2Vx))) == 2*ref_dot exactly; lexicographic (d, orig_idx) min.
__global__ void __launch_bounds__(1024, 1)
k_knn(const float* __restrict__ xyz, float* __restrict__ out, int n) {
    extern __shared__ char smem[];
    float4* sv = (float4*)smem;                         // 8192 * 16B
    unsigned short* sidx = (unsigned short*)(smem + NVERT * sizeof(float4));
    for (int j = threadIdx.x; j < NVERT; j += blockDim.x) {
        sv[j] = g_vs[j];
        sidx[j] = g_vsidx[j];
    }
    __syncthreads();

    float mnx, mny, mnz, dx, dy, dz;
    grid_params(mnx, mny, mnz, dx, dy, dz);
    float ivx = __fdiv_rn((float)GRES, dx);
    float ivy = __fdiv_rn((float)GRES, dy);
    float ivz = __fdiv_rn((float)GRES, dz);
    float* pout = out + 3 * NVERT;

    for (int i = blockIdx.x * blockDim.x + threadIdx.x; i < n;
         i += gridDim.x * blockDim.x) {
        int p = g_perm[i];   // spatially coherent across warp lanes
        float px = xyz[3 * p], py = xyz[3 * p + 1], pz = xyz[3 * p + 2];
        int cx = min(max((int)floorf((px - mnx) * ivx), 0), GRES - 1);
        int cy = min(max((int)floorf((py - mny) * ivy), 0), GRES - 1);
        int cz = min(max((int)floorf((pz - mnz) * ivz), 0), GRES - 1);

        // ---- phase A: geometric upper bound ----
        float bestD = 3.402823466e38f;
        for (int w = 1; w < GRES; w++) {
            int x0 = max(cx - w, 0), x1 = min(cx + w, GRES - 1);
            int y0 = max(cy - w, 0), y1 = min(cy + w, GRES - 1);
            int z0 = max(cz - w, 0), z1 = min(cz + w, GRES - 1);
            for (int ix = x0; ix <= x1; ix++)
                for (int iy = y0; iy <= y1; iy++) {
                    int row = (ix * GRES + iy) * GRES;
                    int s = v_off[row + z0];
                    int e = v_off[row + z1 + 1];
                    for (int j = s; j < e; j++) {
                        float4 V = sv[j];
                        float ddx = px - 0.5f * V.x;
                        float ddy = py - 0.5f * V.y;
                        float ddz = pz - 0.5f * V.z;
                        float D = fmaf(ddz, ddz, fmaf(ddy, ddy, ddx * ddx));
                        bestD = fminf(bestD, D);
                    }
                }
            if (bestD < 3.0e38f) break;
        }

        // ---- phase B: exact rescan of sphere bounding box ----
        float R = sqrtf(bestD + 1e-3f) + 1e-3f;
        int x0 = min(max((int)floorf((px - R - mnx) * ivx), 0), GRES - 1);
        int x1 = min(max((int)floorf((px + R - mnx) * ivx), 0), GRES - 1);
        int y0 = min(max((int)floorf((py - R - mny) * ivy), 0), GRES - 1);
        int y1 = min(max((int)floorf((py + R - mny) * ivy), 0), GRES - 1);
        int z0 = min(max((int)floorf((pz - R - mnz) * ivz), 0), GRES - 1);
        int z1 = min(max((int)floorf((pz + R - mnz) * ivz), 0), GRES - 1);

        float bd = 3.402823466e38f;
        int bi = 0x7FFFFFFF;
        for (int ix = x0; ix <= x1; ix++)
            for (int iy = y0; iy <= y1; iy++) {
                int row = (ix * GRES + iy) * GRES;
                int s = v_off[row + z0];
                int e = v_off[row + z1 + 1];
                for (int j = s; j < e; j++) {
                    float4 V = sv[j];
                    float t2 = fmaf(pz, V.z, fmaf(py, V.y, __fmul_rn(px, V.x)));
                    float d = __fsub_rn(V.w, t2);
                    int oi = sidx[j];
                    if (d < bd || (d == bd && oi < bi)) { bd = d; bi = oi; }
                }
            }
        pout[p] = (float)bi;
    }
}

// ---------------- launch ----------------
extern "C" void kernel_launch(void* const* d_in, const int* in_sizes, int n_in,
                              void* d_out, int out_size) {
    const float* xyz = (const float*)d_in[0];
    int n = in_sizes[0] / 3;
    float* out = (float*)d_out;

    k_init<<<256, 256>>>();
    k_minmax<<<148, 256>>>(xyz, n);
    k_vidhist<<<1024, 256>>>(xyz, n);

    int* d_ghist; cudaGetSymbolAddress((void**)&d_ghist, g_hist);
    int* d_goff;  cudaGetSymbolAddress((void**)&d_goff,  g_off);
    int* d_gcur;  cudaGetSymbolAddress((void**)&d_gcur,  g_cur);
    int* d_vhist; cudaGetSymbolAddress((void**)&d_vhist, v_hist);
    int* d_voff;  cudaGetSymbolAddress((void**)&d_voff,  v_off);
    int* d_vcur;  cudaGetSymbolAddress((void**)&d_vcur,  v_cur);

    k_scan_a<<<SCANB, 512>>>(d_ghist);
    k_scan_b<<<1, 512>>>(d_goff, n);
    k_scan_c<<<SCANB, 512>>>(d_ghist, d_goff, d_gcur);
    k_scatter<<<1024, 256>>>(n);
    k_select<<<NVERT, 128>>>(xyz, out, n);

    k_vbin<<<16, 512>>>();
    k_scan_a<<<SCANB, 512>>>(d_vhist);
    k_scan_b<<<1, 512>>>(d_voff, NVERT);
    k_scan_c<<<SCANB, 512>>>(d_vhist, d_voff, d_vcur);
    k_vscatter<<<16, 512>>>();

    int smem = NVERT * (int)sizeof(float4) + NVERT * (int)sizeof(unsigned short);
    cudaFuncSetAttribute(k_knn, cudaFuncAttributeMaxDynamicSharedMemorySize, smem);
    k_knn<<<148, 1024, smem>>>(xyz, out, n);
}